// round 8
// baseline (speedup 1.0000x reference)
#include <cuda_runtime.h>
#include <math.h>

#define N_NODES 8192
#define MAXD 128
constexpr int KC = 32;   // GEMM k-chunk

// ---------------- scratch (device globals) ----------------------------------
__device__ __align__(16) float d_msg[N_NODES * 128];
__device__ __align__(16) float d_g  [N_NODES * 128];
__device__ __align__(16) float d_f  [N_NODES * 256];   // [unused | h]
__device__ float d_dinv[N_NODES];
__device__ int   d_cnt [N_NODES];
__device__ int   d_nbr [N_NODES * MAXD];

// ---------------- packed f32x2 helpers (PTX-only) ----------------------------
__device__ __forceinline__ unsigned long long f2pack(float lo, float hi) {
    unsigned long long r;
    asm("mov.b64 %0, {%1, %2};" : "=l"(r) : "f"(lo), "f"(hi));
    return r;
}
__device__ __forceinline__ void f2unpack(unsigned long long p, float& lo, float& hi) {
    asm("mov.b64 {%0, %1}, %2;" : "=f"(lo), "=f"(hi) : "l"(p));
}
__device__ __forceinline__ void ffma2(unsigned long long& d,
                                      unsigned long long a, unsigned long long b) {
    asm("fma.rn.f32x2 %0, %1, %2, %0;" : "+l"(d) : "l"(a), "l"(b));
}

// ---------------- per-row adjacency scan (2 batches of 4 float4) ------------
__device__ __forceinline__ void scan_row(const float* __restrict__ adj, int row)
{
    __shared__ int s_cnt;
    const int tid = threadIdx.x;
    if (tid == 0) s_cnt = 0;
    __syncthreads();

    const float4* a4 = (const float4*)(adj + (size_t)row * N_NODES);
    int* nbr = d_nbr + (size_t)row * MAXD;

#pragma unroll
    for (int half = 0; half < 2; half++) {
        float4 v[4];
#pragma unroll
        for (int u = 0; u < 4; u++)
            v[u] = __ldcs(&a4[tid + (half * 4 + u) * 256]);
#pragma unroll
        for (int u = 0; u < 4; u++) {
            const int base = (tid + (half * 4 + u) * 256) * 4;
            if (v[u].x != 0.f) { int p = atomicAdd(&s_cnt, 1); if (p < MAXD) nbr[p] = base + 0; }
            if (v[u].y != 0.f) { int p = atomicAdd(&s_cnt, 1); if (p < MAXD) nbr[p] = base + 1; }
            if (v[u].z != 0.f) { int p = atomicAdd(&s_cnt, 1); if (p < MAXD) nbr[p] = base + 2; }
            if (v[u].w != 0.f) { int p = atomicAdd(&s_cnt, 1); if (p < MAXD) nbr[p] = base + 3; }
        }
    }
    __syncthreads();
    if (tid == 0) {
        int cn = s_cnt;
        d_cnt[row]  = cn < MAXD ? cn : MAXD;
        d_dinv[row] = rsqrtf((float)cn + 1.0f);   // +1 self loop
    }
}

// ---------------- register-tiled GEMM (BR rows) with packed f32x2 FMA -------
template <int BR, int K, int M, bool RELU>
__device__ __forceinline__ void mlp_gemm(
        const float* in_s, int in_ss,
        const float* __restrict__ W, const float* __restrict__ bias,
        float* wt_s,
        float* out_s, int out_ss,
        float* out_g, int out_gs, int row0)
{
    constexpr int TX  = M / 4;
    constexpr int TY  = 256 / TX;
    constexpr int RPT = BR / TY;
    constexpr int G   = M / 4;

    const int tid = threadIdx.x;
    const int tx  = tid % TX;
    const int ty  = tid / TX;

    unsigned long long acc01[RPT], acc23[RPT];
#pragma unroll
    for (int r = 0; r < RPT; r++) { acc01[r] = 0ull; acc23[r] = 0ull; }

    for (int k0 = 0; k0 < K; k0 += KC) {
        {   // weight tile, transposed + rotated (conflict-free STS/LDS)
            int v = tid & 7;
#pragma unroll
            for (int m = tid >> 3; m < M; m += 32) {
                float4 w = *(const float4*)(W + (size_t)m * K + k0 + v * 4);
                int g = m >> 2, ml = m & 3;
                float wc[4] = {w.x, w.y, w.z, w.w};
#pragma unroll
                for (int c = 0; c < 4; c++) {
                    int k  = v * 4 + c;
                    int gp = (g + k + (k >> 2)) & (G - 1);
                    wt_s[k * M + gp * 4 + ml] = wc[c];
                }
            }
        }
        __syncthreads();

#pragma unroll
        for (int kv = 0; kv < KC / 4; kv++) {
            unsigned long long w01[4], w23[4];
#pragma unroll
            for (int c = 0; c < 4; c++) {
                int k  = kv * 4 + c;
                int gp = (tx + k + (k >> 2)) & (G - 1);
                float4 w = *(const float4*)&wt_s[k * M + gp * 4];
                w01[c] = f2pack(w.x, w.y);
                w23[c] = f2pack(w.z, w.w);
            }
#pragma unroll
            for (int rr = 0; rr < RPT; rr++) {
                float4 a = *(const float4*)&in_s[(ty * RPT + rr) * in_ss + k0 + kv * 4];
                unsigned long long aa;
                aa = f2pack(a.x, a.x); ffma2(acc01[rr], aa, w01[0]); ffma2(acc23[rr], aa, w23[0]);
                aa = f2pack(a.y, a.y); ffma2(acc01[rr], aa, w01[1]); ffma2(acc23[rr], aa, w23[1]);
                aa = f2pack(a.z, a.z); ffma2(acc01[rr], aa, w01[2]); ffma2(acc23[rr], aa, w23[2]);
                aa = f2pack(a.w, a.w); ffma2(acc01[rr], aa, w01[3]); ffma2(acc23[rr], aa, w23[3]);
            }
        }
        __syncthreads();
    }

    float4 bb = make_float4(0.f, 0.f, 0.f, 0.f);
    if (bias) bb = *(const float4*)(bias + tx * 4);

#pragma unroll
    for (int rr = 0; rr < RPT; rr++) {
        int r = ty * RPT + rr;
        float4 o;
        f2unpack(acc01[rr], o.x, o.y);
        f2unpack(acc23[rr], o.z, o.w);
        o.x += bb.x; o.y += bb.y; o.z += bb.z; o.w += bb.w;
        if (RELU) {
            o.x = fmaxf(o.x, 0.f); o.y = fmaxf(o.y, 0.f);
            o.z = fmaxf(o.z, 0.f); o.w = fmaxf(o.w, 0.f);
        }
        if (out_s) *(float4*)&out_s[r * out_ss + tx * 4] = o;
        if (out_g) *(float4*)(out_g + (size_t)(row0 + r) * out_gs + tx * 4) = o;
    }
}

// ---------------- fused: encoder blocks (0..255) + scan blocks (256..) ------
__global__ void __launch_bounds__(256, 5)
enc_scan_kernel(const float* __restrict__ x,
                const float* __restrict__ w1, const float* __restrict__ b1,
                const float* __restrict__ w2, const float* __restrict__ b2,
                const float* __restrict__ wg,
                float* __restrict__ f, float* __restrict__ msg,
                const float* __restrict__ adj)
{
    if ((int)blockIdx.x >= N_NODES / 32) {
        scan_row(adj, (int)blockIdx.x - N_NODES / 32);
        return;
    }

    extern __shared__ float esm[];
    float* s_a = esm;            // 4096: x tile, later h
    float* s_b = esm + 4096;     // 2048: h1
    float* wt  = esm + 6144;     // 4096: weight tile

    const int tid  = threadIdx.x;
    const int row0 = blockIdx.x * 32;

    {   // load x tile [32,32]
        int r = tid >> 3, vv = tid & 7;
        *(float4*)&s_a[r * 32 + vv * 4] =
            *(const float4*)(x + (size_t)(row0 + r) * 32 + vv * 4);
    }
    __syncthreads();

    mlp_gemm<32, 32, 64, true>(s_a, 32, w1, b1, wt, s_b, 64, nullptr, 0, 0);
    __syncthreads();
    mlp_gemm<32, 64, 128, true>(s_b, 64, w2, b2, wt, s_a, 128, f + 128, 256, row0);
    __syncthreads();
    mlp_gemm<32, 128, 128, false>(s_a, 128, wg, nullptr, wt, nullptr, 0, msg, 128, row0);
}

// ---------------- aggregation: one row per 128-thread block (grid=8192) -----
__global__ void __launch_bounds__(128)
agg_kernel(const float* __restrict__ msg, const float* __restrict__ bg,
           float* __restrict__ g)
{
    const int row = blockIdx.x;
    const int c   = threadIdx.x;

    __shared__ int   s_idx[MAXD];
    __shared__ float s_dj [MAXD];

    const int   cnt = d_cnt[row];
    const float di  = d_dinv[row];

    if (c < cnt) {
        int j = d_nbr[(size_t)row * MAXD + c];
        s_idx[c] = j;
        s_dj[c]  = d_dinv[j];
    }
    __syncthreads();

    float a0 = di * msg[(size_t)row * 128 + c];   // self-loop term
    float a1 = 0.f, a2 = 0.f, a3 = 0.f;
    int k = 0;
    for (; k + 3 < cnt; k += 4) {                 // 4 gathers in flight
        a0 += s_dj[k]     * msg[(size_t)s_idx[k]     * 128 + c];
        a1 += s_dj[k + 1] * msg[(size_t)s_idx[k + 1] * 128 + c];
        a2 += s_dj[k + 2] * msg[(size_t)s_idx[k + 2] * 128 + c];
        a3 += s_dj[k + 3] * msg[(size_t)s_idx[k + 3] * 128 + c];
    }
    for (; k < cnt; k++)
        a0 += s_dj[k] * msg[(size_t)s_idx[k] * 128 + c];

    float v = di * ((a0 + a1) + (a2 + a3)) + bg[c];
    g[(size_t)row * 128 + c] = fmaxf(v, 0.f);
}

// ---------------- decoder MLP: 16 rows/block, grid=512 -----------------------
__global__ void __launch_bounds__(256, 4)
decoder_mlp(const float* __restrict__ g_in,
            const float* __restrict__ wd,  const float* __restrict__ bd,
            const float* __restrict__ wp1, const float* __restrict__ bp1,
            const float* __restrict__ wp2, const float* __restrict__ bp2,
            const float* __restrict__ wo,  const float* __restrict__ bo,
            const float* __restrict__ mask,
            const float* __restrict__ f_g,
            float* __restrict__ out)
{
    extern __shared__ float sm[];
    float* s_f  = sm;            // [16][256]  4096
    float* s_t  = sm + 4096;     // [16][128]  2048: g, then p1
    float* wt   = sm + 6144;     // 4096: weight tile
    float* s_wo = sm + 10240;    // [8][64]
    float* s_bo = sm + 10752;    // [8]
    float* s_p2 = s_f;           // reuse after s_f dead

    const int tid  = threadIdx.x;
    const int row0 = blockIdx.x * 16;

    for (int i = tid; i < 16 * 32; i += 256) {   // h half of f
        int r = i >> 5, vv = i & 31;
        *(float4*)&s_f[r * 256 + 128 + vv * 4] =
            *(const float4*)(f_g + (size_t)(row0 + r) * 256 + 128 + vv * 4);
    }
    for (int i = tid; i < 16 * 32; i += 256) {   // g tile
        int r = i >> 5, vv = i & 31;
        *(float4*)&s_t[r * 128 + vv * 4] =
            *(const float4*)(g_in + (size_t)(row0 + r) * 128 + vv * 4);
    }
    for (int i = tid; i < 512; i += 256) s_wo[i] = wo[i];
    if (tid < 8) s_bo[tid] = bo[tid];
    __syncthreads();

    mlp_gemm<16, 128, 128, true>(s_t, 128, wd, bd, wt, s_f, 256, nullptr, 0, 0);
    __syncthreads();
    mlp_gemm<16, 256, 128, true>(s_f, 256, wp1, bp1, wt, s_t, 128, nullptr, 0, 0);
    __syncthreads();
    mlp_gemm<16, 128, 64, true>(s_t, 128, wp2, bp2, wt, s_p2, 64, nullptr, 0, 0);
    __syncthreads();

    if (tid < 128) {   // out = (p2 @ wo^T + bo) * mask : 16 rows x 8 cols
        const int r = tid >> 3, m = tid & 7;
        float acc = 0.f;
#pragma unroll
        for (int k = 0; k < 64; k++) acc += s_p2[r * 64 + k] * s_wo[m * 64 + k];
        out[(size_t)(row0 + r) * 8 + m] = (acc + s_bo[m]) * mask[row0 + r];
    }
}

// ---------------- launch -----------------------------------------------------
extern "C" void kernel_launch(void* const* d_in, const int* in_sizes, int n_in,
                              void* d_out, int out_size)
{
    const float* x    = (const float*)d_in[0];
    const float* adj  = (const float*)d_in[1];
    const float* mask = (const float*)d_in[2];
    const float* w1   = (const float*)d_in[3];
    const float* b1   = (const float*)d_in[4];
    const float* w2   = (const float*)d_in[5];
    const float* b2   = (const float*)d_in[6];
    const float* wg   = (const float*)d_in[7];
    const float* bg   = (const float*)d_in[8];
    const float* wd   = (const float*)d_in[9];
    const float* bd   = (const float*)d_in[10];
    const float* wp1  = (const float*)d_in[11];
    const float* bp1  = (const float*)d_in[12];
    const float* wp2  = (const float*)d_in[13];
    const float* bp2  = (const float*)d_in[14];
    const float* wo   = (const float*)d_in[15];
    const float* bo   = (const float*)d_in[16];
    float* out = (float*)d_out;

    float *p_msg, *p_f, *p_g;
    cudaGetSymbolAddress((void**)&p_msg, d_msg);
    cudaGetSymbolAddress((void**)&p_f,   d_f);
    cudaGetSymbolAddress((void**)&p_g,   d_g);

    const int ENC_SMEM = (4096 + 2048 + 4096) * 4;            // 40960 B
    const int DEC_SMEM = (4096 + 2048 + 4096 + 512 + 8) * 4;  // 43040 B
    static int smem_set = 0;
    if (!smem_set) {
        cudaFuncSetAttribute(enc_scan_kernel,
                             cudaFuncAttributeMaxDynamicSharedMemorySize, ENC_SMEM);
        cudaFuncSetAttribute(decoder_mlp,
                             cudaFuncAttributeMaxDynamicSharedMemorySize, DEC_SMEM);
        smem_set = 1;
    }

    enc_scan_kernel<<<N_NODES / 32 + N_NODES, 256, ENC_SMEM>>>(
        x, w1, b1, w2, b2, wg, p_f, p_msg, adj);
    agg_kernel<<<N_NODES, 128>>>(p_msg, bg, p_g);
    decoder_mlp<<<N_NODES / 16, 256, DEC_SMEM>>>(
        p_g, wd, bd, wp1, bp1, wp2, bp2, wo, bo, mask, p_f, out);
}

// round 9
// speedup vs baseline: 1.0757x; 1.0757x over previous
#include <cuda_runtime.h>
#include <math.h>
#include <stdint.h>

#define N_NODES 8192
#define MAXD 128
constexpr int KC = 32;   // GEMM k-chunk

// ---------------- scratch (device globals) ----------------------------------
__device__ __align__(16) float d_msg[N_NODES * 128];
__device__ __align__(16) float d_g  [N_NODES * 128];
__device__ __align__(16) float d_f  [N_NODES * 256];   // [unused | h]
__device__ float d_dinv[N_NODES];
__device__ int   d_cnt [N_NODES];
__device__ int   d_nbr [N_NODES * MAXD];

// transposed weights, [K][M] row-major
__device__ __align__(16) float d_wt1 [32 * 64];
__device__ __align__(16) float d_wt2 [64 * 128];
__device__ __align__(16) float d_wtg [128 * 128];
__device__ __align__(16) float d_wtd [128 * 128];
__device__ __align__(16) float d_wtp1[256 * 128];
__device__ __align__(16) float d_wtp2[128 * 64];

// ---------------- cp.async helpers ------------------------------------------
__device__ __forceinline__ uint32_t smem_u32(const void* p) {
    return (uint32_t)__cvta_generic_to_shared(p);
}
#define CP_ASYNC16(dst_u32, src_ptr) \
    asm volatile("cp.async.cg.shared.global [%0], [%1], 16;" \
                 :: "r"(dst_u32), "l"(src_ptr) : "memory")
#define CP_COMMIT() asm volatile("cp.async.commit_group;" ::: "memory")
#define CP_WAIT0()  asm volatile("cp.async.wait_group 0;"  ::: "memory")

// ---------------- packed f32x2 helpers (PTX-only) ----------------------------
__device__ __forceinline__ unsigned long long f2pack(float lo, float hi) {
    unsigned long long r;
    asm("mov.b64 %0, {%1, %2};" : "=l"(r) : "f"(lo), "f"(hi));
    return r;
}
__device__ __forceinline__ void f2unpack(unsigned long long p, float& lo, float& hi) {
    asm("mov.b64 {%0, %1}, %2;" : "=f"(lo), "=f"(hi) : "l"(p));
}
__device__ __forceinline__ void ffma2(unsigned long long& d,
                                      unsigned long long a, unsigned long long b) {
    asm("fma.rn.f32x2 %0, %1, %2, %0;" : "+l"(d) : "l"(a), "l"(b));
}

// ---------------- weight transpose prep --------------------------------------
__global__ void __launch_bounds__(256)
transpose_weights(const float* __restrict__ w1, const float* __restrict__ w2,
                  const float* __restrict__ wg, const float* __restrict__ wd,
                  const float* __restrict__ wp1, const float* __restrict__ wp2)
{
    const float* Ws[6]  = {w1, w2, wg, wd, wp1, wp2};
    float*       WTs[6] = {d_wt1, d_wt2, d_wtg, d_wtd, d_wtp1, d_wtp2};
    const int    Ms[6]  = {64, 128, 128, 128, 128, 64};
    const int    Ks[6]  = {32, 64, 128, 128, 256, 128};

    int gtid = blockIdx.x * blockDim.x + threadIdx.x;
    int nth  = gridDim.x * blockDim.x;
#pragma unroll
    for (int mi = 0; mi < 6; mi++) {
        int M = Ms[mi], K = Ks[mi], n = M * K;
        const float* W = Ws[mi];
        float* WT = WTs[mi];
        for (int e = gtid; e < n; e += nth) {
            int m = e / K, k = e % K;        // coalesced read over k
            WT[k * M + m] = W[e];
        }
    }
}

// ---------------- per-row adjacency scan (MLP=8 batched loads) ---------------
__device__ __forceinline__ void scan_row(const float* __restrict__ adj, int row)
{
    __shared__ int s_cnt;
    const int tid = threadIdx.x;
    if (tid == 0) s_cnt = 0;
    __syncthreads();

    const float4* a4 = (const float4*)(adj + (size_t)row * N_NODES);
    int* nbr = d_nbr + (size_t)row * MAXD;

    float4 v[8];
#pragma unroll
    for (int u = 0; u < 8; u++)
        v[u] = __ldcs(&a4[tid + u * 256]);     // 8 independent loads in flight

#pragma unroll
    for (int u = 0; u < 8; u++) {
        const int base = (tid + u * 256) * 4;
        if (v[u].x != 0.f) { int p = atomicAdd(&s_cnt, 1); if (p < MAXD) nbr[p] = base + 0; }
        if (v[u].y != 0.f) { int p = atomicAdd(&s_cnt, 1); if (p < MAXD) nbr[p] = base + 1; }
        if (v[u].z != 0.f) { int p = atomicAdd(&s_cnt, 1); if (p < MAXD) nbr[p] = base + 2; }
        if (v[u].w != 0.f) { int p = atomicAdd(&s_cnt, 1); if (p < MAXD) nbr[p] = base + 3; }
    }
    __syncthreads();
    if (tid == 0) {
        int cn = s_cnt;
        d_cnt[row]  = cn < MAXD ? cn : MAXD;
        d_dinv[row] = rsqrtf((float)cn + 1.0f);   // +1 self loop
    }
}

// ---------------- GEMM: cp.async double-buffered weights, f32x2 FMA ----------
// WT is PRE-TRANSPOSED [K][M]. wt_s must hold 2*KC*M floats.
template <int BR, int K, int M, bool RELU>
__device__ __forceinline__ void mlp_gemm(
        const float* in_s, int in_ss,
        const float* __restrict__ WT, const float* __restrict__ bias,
        float* wt_s,
        float* out_s, int out_ss,
        float* out_g, int out_gs, int row0)
{
    constexpr int TX  = M / 4;
    constexpr int TY  = 256 / TX;
    constexpr int RPT = BR / TY;
    constexpr int CH  = K / KC;
    constexpr int CPB = (KC * M / 4) / 256;   // float4 copies per thread per chunk

    const int tid = threadIdx.x;
    const int tx  = tid % TX;
    const int ty  = tid / TX;

    unsigned long long acc01[RPT], acc23[RPT];
#pragma unroll
    for (int r = 0; r < RPT; r++) { acc01[r] = 0ull; acc23[r] = 0ull; }

    const uint32_t wt_base = smem_u32(wt_s);

    {   // preload chunk 0
        uint32_t dst = wt_base + tid * 16;
        const float* src = WT + tid * 4;
#pragma unroll
        for (int i = 0; i < CPB; i++)
            CP_ASYNC16(dst + i * 4096, src + i * 1024);
        CP_COMMIT();
    }

#pragma unroll
    for (int ch = 0; ch < CH; ch++) {
        CP_WAIT0();
        __syncthreads();   // chunk ch resident; prior chunk's readers done

        if (ch + 1 < CH) { // prefetch chunk ch+1 into the other buffer
            uint32_t dst = wt_base + (uint32_t)(((ch + 1) & 1) * KC * M * 4) + tid * 16;
            const float* src = WT + (size_t)(ch + 1) * KC * M + tid * 4;
#pragma unroll
            for (int i = 0; i < CPB; i++)
                CP_ASYNC16(dst + i * 4096, src + i * 1024);
            CP_COMMIT();
        }

        const float* buf = wt_s + (ch & 1) * (KC * M);
        const int k0 = ch * KC;

#pragma unroll
        for (int kv = 0; kv < KC / 4; kv++) {
            unsigned long long w01[4], w23[4];
#pragma unroll
            for (int c = 0; c < 4; c++) {
                float4 w = *(const float4*)&buf[(kv * 4 + c) * M + tx * 4];
                w01[c] = f2pack(w.x, w.y);
                w23[c] = f2pack(w.z, w.w);
            }
#pragma unroll
            for (int rr = 0; rr < RPT; rr++) {
                float4 a = *(const float4*)&in_s[(ty * RPT + rr) * in_ss + k0 + kv * 4];
                unsigned long long aa;
                aa = f2pack(a.x, a.x); ffma2(acc01[rr], aa, w01[0]); ffma2(acc23[rr], aa, w23[0]);
                aa = f2pack(a.y, a.y); ffma2(acc01[rr], aa, w01[1]); ffma2(acc23[rr], aa, w23[1]);
                aa = f2pack(a.z, a.z); ffma2(acc01[rr], aa, w01[2]); ffma2(acc23[rr], aa, w23[2]);
                aa = f2pack(a.w, a.w); ffma2(acc01[rr], aa, w01[3]); ffma2(acc23[rr], aa, w23[3]);
            }
        }
        // no trailing barrier: next iteration's wait+sync protects buffer reuse
    }

    float4 bb = make_float4(0.f, 0.f, 0.f, 0.f);
    if (bias) bb = *(const float4*)(bias + tx * 4);

#pragma unroll
    for (int rr = 0; rr < RPT; rr++) {
        int r = ty * RPT + rr;
        float4 o;
        f2unpack(acc01[rr], o.x, o.y);
        f2unpack(acc23[rr], o.z, o.w);
        o.x += bb.x; o.y += bb.y; o.z += bb.z; o.w += bb.w;
        if (RELU) {
            o.x = fmaxf(o.x, 0.f); o.y = fmaxf(o.y, 0.f);
            o.z = fmaxf(o.z, 0.f); o.w = fmaxf(o.w, 0.f);
        }
        if (out_s) *(float4*)&out_s[r * out_ss + tx * 4] = o;
        if (out_g) *(float4*)(out_g + (size_t)(row0 + r) * out_gs + tx * 4) = o;
    }
}

// ---------------- fused: encoder blocks (0..255) + scan blocks (256..) ------
__global__ void __launch_bounds__(256, 4)
enc_scan_kernel(const float* __restrict__ x,
                const float* __restrict__ b1, const float* __restrict__ b2,
                float* __restrict__ f, float* __restrict__ msg,
                const float* __restrict__ adj)
{
    if ((int)blockIdx.x >= N_NODES / 32) {
        scan_row(adj, (int)blockIdx.x - N_NODES / 32);
        return;
    }

    extern __shared__ float esm[];
    float* s_a = esm;            // 4096: x tile, later h
    float* s_b = esm + 4096;     // 2048: h1
    float* wt  = esm + 6144;     // 8192: double-buffered weight tiles

    const int tid  = threadIdx.x;
    const int row0 = blockIdx.x * 32;

    {   // load x tile [32,32]
        int r = tid >> 3, vv = tid & 7;
        *(float4*)&s_a[r * 32 + vv * 4] =
            *(const float4*)(x + (size_t)(row0 + r) * 32 + vv * 4);
    }
    __syncthreads();

    mlp_gemm<32, 32, 64, true>(s_a, 32, d_wt1, b1, wt, s_b, 64, nullptr, 0, 0);
    __syncthreads();
    mlp_gemm<32, 64, 128, true>(s_b, 64, d_wt2, b2, wt, s_a, 128, f + 128, 256, row0);
    __syncthreads();
    mlp_gemm<32, 128, 128, false>(s_a, 128, d_wtg, nullptr, wt, nullptr, 0, msg, 128, row0);
}

// ---------------- aggregation: one row per 128-thread block (grid=8192) -----
__global__ void __launch_bounds__(128)
agg_kernel(const float* __restrict__ msg, const float* __restrict__ bg,
           float* __restrict__ g)
{
    const int row = blockIdx.x;
    const int c   = threadIdx.x;

    __shared__ int   s_idx[MAXD];
    __shared__ float s_dj [MAXD];

    const int   cnt = d_cnt[row];
    const float di  = d_dinv[row];

    if (c < cnt) {
        int j = d_nbr[(size_t)row * MAXD + c];
        s_idx[c] = j;
        s_dj[c]  = d_dinv[j];
    }
    __syncthreads();

    float a0 = di * msg[(size_t)row * 128 + c];   // self-loop term
    float a1 = 0.f, a2 = 0.f, a3 = 0.f;
    int k = 0;
    for (; k + 3 < cnt; k += 4) {                 // 4 gathers in flight
        a0 += s_dj[k]     * msg[(size_t)s_idx[k]     * 128 + c];
        a1 += s_dj[k + 1] * msg[(size_t)s_idx[k + 1] * 128 + c];
        a2 += s_dj[k + 2] * msg[(size_t)s_idx[k + 2] * 128 + c];
        a3 += s_dj[k + 3] * msg[(size_t)s_idx[k + 3] * 128 + c];
    }
    for (; k < cnt; k++)
        a0 += s_dj[k] * msg[(size_t)s_idx[k] * 128 + c];

    float v = di * ((a0 + a1) + (a2 + a3)) + bg[c];
    g[(size_t)row * 128 + c] = fmaxf(v, 0.f);
}

// ---------------- decoder MLP: 16 rows/block, grid=512 -----------------------
__global__ void __launch_bounds__(256, 3)
decoder_mlp(const float* __restrict__ g_in,
            const float* __restrict__ bd,  const float* __restrict__ bp1,
            const float* __restrict__ bp2,
            const float* __restrict__ wo,  const float* __restrict__ bo,
            const float* __restrict__ mask,
            const float* __restrict__ f_g,
            float* __restrict__ out)
{
    extern __shared__ float sm[];
    float* s_f  = sm;            // [16][256]  4096
    float* s_t  = sm + 4096;     // [16][128]  2048: g, then p1
    float* wt   = sm + 6144;     // 8192: double-buffered weight tiles
    float* s_wo = sm + 14336;    // [8][64]
    float* s_bo = sm + 14848;    // [8]
    float* s_p2 = s_f;           // reuse after s_f dead

    const int tid  = threadIdx.x;
    const int row0 = blockIdx.x * 16;

    for (int i = tid; i < 16 * 32; i += 256) {   // h half of f
        int r = i >> 5, vv = i & 31;
        *(float4*)&s_f[r * 256 + 128 + vv * 4] =
            *(const float4*)(f_g + (size_t)(row0 + r) * 256 + 128 + vv * 4);
    }
    for (int i = tid; i < 16 * 32; i += 256) {   // g tile
        int r = i >> 5, vv = i & 31;
        *(float4*)&s_t[r * 128 + vv * 4] =
            *(const float4*)(g_in + (size_t)(row0 + r) * 128 + vv * 4);
    }
    for (int i = tid; i < 512; i += 256) s_wo[i] = wo[i];
    if (tid < 8) s_bo[tid] = bo[tid];
    __syncthreads();

    mlp_gemm<16, 128, 128, true>(s_t, 128, d_wtd, bd, wt, s_f, 256, nullptr, 0, 0);
    __syncthreads();
    mlp_gemm<16, 256, 128, true>(s_f, 256, d_wtp1, bp1, wt, s_t, 128, nullptr, 0, 0);
    __syncthreads();
    mlp_gemm<16, 128, 64, true>(s_t, 128, d_wtp2, bp2, wt, s_p2, 64, nullptr, 0, 0);
    __syncthreads();

    if (tid < 128) {   // out = (p2 @ wo^T + bo) * mask : 16 rows x 8 cols
        const int r = tid >> 3, m = tid & 7;
        float acc = 0.f;
#pragma unroll
        for (int k = 0; k < 64; k++) acc += s_p2[r * 64 + k] * s_wo[m * 64 + k];
        out[(size_t)(row0 + r) * 8 + m] = (acc + s_bo[m]) * mask[row0 + r];
    }
}

// ---------------- launch -----------------------------------------------------
extern "C" void kernel_launch(void* const* d_in, const int* in_sizes, int n_in,
                              void* d_out, int out_size)
{
    const float* x    = (const float*)d_in[0];
    const float* adj  = (const float*)d_in[1];
    const float* mask = (const float*)d_in[2];
    const float* w1   = (const float*)d_in[3];
    const float* b1   = (const float*)d_in[4];
    const float* w2   = (const float*)d_in[5];
    const float* b2   = (const float*)d_in[6];
    const float* wg   = (const float*)d_in[7];
    const float* bg   = (const float*)d_in[8];
    const float* wd   = (const float*)d_in[9];
    const float* bd   = (const float*)d_in[10];
    const float* wp1  = (const float*)d_in[11];
    const float* bp1  = (const float*)d_in[12];
    const float* wp2  = (const float*)d_in[13];
    const float* bp2  = (const float*)d_in[14];
    const float* wo   = (const float*)d_in[15];
    const float* bo   = (const float*)d_in[16];
    float* out = (float*)d_out;

    float *p_msg, *p_f, *p_g;
    cudaGetSymbolAddress((void**)&p_msg, d_msg);
    cudaGetSymbolAddress((void**)&p_f,   d_f);
    cudaGetSymbolAddress((void**)&p_g,   d_g);

    const int ENC_SMEM = (4096 + 2048 + 8192) * 4;            // 57344 B
    const int DEC_SMEM = (4096 + 2048 + 8192 + 512 + 8) * 4;  // 59424 B
    static int smem_set = 0;
    if (!smem_set) {
        cudaFuncSetAttribute(enc_scan_kernel,
                             cudaFuncAttributeMaxDynamicSharedMemorySize, ENC_SMEM);
        cudaFuncSetAttribute(decoder_mlp,
                             cudaFuncAttributeMaxDynamicSharedMemorySize, DEC_SMEM);
        smem_set = 1;
    }

    transpose_weights<<<128, 256>>>(w1, w2, wg, wd, wp1, wp2);
    enc_scan_kernel<<<N_NODES / 32 + N_NODES, 256, ENC_SMEM>>>(
        x, b1, b2, p_f, p_msg, adj);
    agg_kernel<<<N_NODES, 128>>>(p_msg, bg, p_g);
    decoder_mlp<<<N_NODES / 16, 256, DEC_SMEM>>>(
        p_g, bd, bp1, bp2, wo, bo, mask, p_f, out);
}

// round 10
// speedup vs baseline: 1.2362x; 1.1491x over previous
#include <cuda_runtime.h>
#include <math.h>
#include <stdint.h>

#define N_NODES 8192
#define MAXD 128
constexpr int KC = 32;   // GEMM k-chunk

// ---------------- scratch (device globals) ----------------------------------
__device__ __align__(16) float d_msg[N_NODES * 128];
__device__ __align__(16) float d_g  [N_NODES * 128];
__device__ __align__(16) float d_f  [N_NODES * 256];   // [unused | h]
__device__ float d_dinv[N_NODES];
__device__ int   d_cnt [N_NODES];
__device__ int   d_nbr [N_NODES * MAXD];

// transposed weights, [K][M] row-major
__device__ __align__(16) float d_wt1 [32 * 64];
__device__ __align__(16) float d_wt2 [64 * 128];
__device__ __align__(16) float d_wtg [128 * 128];
__device__ __align__(16) float d_wtd [128 * 128];
__device__ __align__(16) float d_wtp1[256 * 128];
__device__ __align__(16) float d_wtp2[128 * 64];

// ---------------- cp.async helpers ------------------------------------------
__device__ __forceinline__ uint32_t smem_u32(const void* p) {
    return (uint32_t)__cvta_generic_to_shared(p);
}
#define CP_ASYNC16(dst_u32, src_ptr) \
    asm volatile("cp.async.cg.shared.global [%0], [%1], 16;" \
                 :: "r"(dst_u32), "l"(src_ptr) : "memory")
#define CP_COMMIT() asm volatile("cp.async.commit_group;" ::: "memory")
#define CP_WAIT0()  asm volatile("cp.async.wait_group 0;"  ::: "memory")

// ---------------- packed f32x2 helpers (PTX-only) ----------------------------
__device__ __forceinline__ unsigned long long f2pack(float lo, float hi) {
    unsigned long long r;
    asm("mov.b64 %0, {%1, %2};" : "=l"(r) : "f"(lo), "f"(hi));
    return r;
}
__device__ __forceinline__ void f2unpack(unsigned long long p, float& lo, float& hi) {
    asm("mov.b64 {%0, %1}, %2;" : "=f"(lo), "=f"(hi) : "l"(p));
}
__device__ __forceinline__ void ffma2(unsigned long long& d,
                                      unsigned long long a, unsigned long long b) {
    asm("fma.rn.f32x2 %0, %1, %2, %0;" : "+l"(d) : "l"(a), "l"(b));
}

// ---------------- weight transpose prep --------------------------------------
__global__ void __launch_bounds__(256)
transpose_weights(const float* __restrict__ w1, const float* __restrict__ w2,
                  const float* __restrict__ wg, const float* __restrict__ wd,
                  const float* __restrict__ wp1, const float* __restrict__ wp2)
{
    const float* Ws[6]  = {w1, w2, wg, wd, wp1, wp2};
    float*       WTs[6] = {d_wt1, d_wt2, d_wtg, d_wtd, d_wtp1, d_wtp2};
    const int    Ms[6]  = {64, 128, 128, 128, 128, 64};
    const int    Ks[6]  = {32, 64, 128, 128, 256, 128};

    int gtid = blockIdx.x * blockDim.x + threadIdx.x;
    int nth  = gridDim.x * blockDim.x;
#pragma unroll
    for (int mi = 0; mi < 6; mi++) {
        int M = Ms[mi], K = Ks[mi], n = M * K;
        const float* W = Ws[mi];
        float* WT = WTs[mi];
        for (int e = gtid; e < n; e += nth) {
            int m = e / K, k = e % K;
            WT[k * M + m] = W[e];
        }
    }
}

// ---------------- per-row adjacency scan (MLP=8 batched loads) ---------------
__device__ __forceinline__ void scan_row(const float* __restrict__ adj, int row)
{
    __shared__ int s_cnt;
    const int tid = threadIdx.x;
    if (tid == 0) s_cnt = 0;
    __syncthreads();

    const float4* a4 = (const float4*)(adj + (size_t)row * N_NODES);
    int* nbr = d_nbr + (size_t)row * MAXD;

    float4 v[8];
#pragma unroll
    for (int u = 0; u < 8; u++)
        v[u] = __ldcs(&a4[tid + u * 256]);

#pragma unroll
    for (int u = 0; u < 8; u++) {
        const int base = (tid + u * 256) * 4;
        if (v[u].x != 0.f) { int p = atomicAdd(&s_cnt, 1); if (p < MAXD) nbr[p] = base + 0; }
        if (v[u].y != 0.f) { int p = atomicAdd(&s_cnt, 1); if (p < MAXD) nbr[p] = base + 1; }
        if (v[u].z != 0.f) { int p = atomicAdd(&s_cnt, 1); if (p < MAXD) nbr[p] = base + 2; }
        if (v[u].w != 0.f) { int p = atomicAdd(&s_cnt, 1); if (p < MAXD) nbr[p] = base + 3; }
    }
    __syncthreads();
    if (tid == 0) {
        int cn = s_cnt;
        d_cnt[row]  = cn < MAXD ? cn : MAXD;
        d_dinv[row] = rsqrtf((float)cn + 1.0f);   // +1 self loop
    }
}

// ---------------- GEMM: cp.async double-buffered weights, f32x2 FMA ----------
// WT is PRE-TRANSPOSED [K][M]. wt_s must hold 2*KC*M floats.
// Activation loads are warp-uniform (broadcast) -> crossbar-cheap; weight
// loads amortized over RPT rows.
template <int BR, int K, int M, bool RELU>
__device__ __forceinline__ void mlp_gemm(
        const float* in_s, int in_ss,
        const float* __restrict__ WT, const float* __restrict__ bias,
        float* wt_s,
        float* out_s, int out_ss,
        float* out_g, int out_gs, int row0)
{
    constexpr int TX  = M / 4;
    constexpr int TY  = 256 / TX;
    constexpr int RPT = BR / TY;
    constexpr int CH  = K / KC;
    constexpr int CPB = (KC * M / 4) / 256;

    const int tid = threadIdx.x;
    const int tx  = tid % TX;
    const int ty  = tid / TX;

    unsigned long long acc01[RPT], acc23[RPT];
#pragma unroll
    for (int r = 0; r < RPT; r++) { acc01[r] = 0ull; acc23[r] = 0ull; }

    const uint32_t wt_base = smem_u32(wt_s);

    {   // preload chunk 0
        uint32_t dst = wt_base + tid * 16;
        const float* src = WT + tid * 4;
#pragma unroll
        for (int i = 0; i < CPB; i++)
            CP_ASYNC16(dst + i * 4096, src + i * 1024);
        CP_COMMIT();
    }

#pragma unroll
    for (int ch = 0; ch < CH; ch++) {
        CP_WAIT0();
        __syncthreads();

        if (ch + 1 < CH) {
            uint32_t dst = wt_base + (uint32_t)(((ch + 1) & 1) * KC * M * 4) + tid * 16;
            const float* src = WT + (size_t)(ch + 1) * KC * M + tid * 4;
#pragma unroll
            for (int i = 0; i < CPB; i++)
                CP_ASYNC16(dst + i * 4096, src + i * 1024);
            CP_COMMIT();
        }

        const float* buf = wt_s + (ch & 1) * (KC * M);
        const int k0 = ch * KC;

#pragma unroll
        for (int kv = 0; kv < KC / 4; kv++) {
            unsigned long long w01[4], w23[4];
#pragma unroll
            for (int c = 0; c < 4; c++) {
                float4 w = *(const float4*)&buf[(kv * 4 + c) * M + tx * 4];
                w01[c] = f2pack(w.x, w.y);
                w23[c] = f2pack(w.z, w.w);
            }
#pragma unroll
            for (int rr = 0; rr < RPT; rr++) {
                float4 a = *(const float4*)&in_s[(ty * RPT + rr) * in_ss + k0 + kv * 4];
                unsigned long long aa;
                aa = f2pack(a.x, a.x); ffma2(acc01[rr], aa, w01[0]); ffma2(acc23[rr], aa, w23[0]);
                aa = f2pack(a.y, a.y); ffma2(acc01[rr], aa, w01[1]); ffma2(acc23[rr], aa, w23[1]);
                aa = f2pack(a.z, a.z); ffma2(acc01[rr], aa, w01[2]); ffma2(acc23[rr], aa, w23[2]);
                aa = f2pack(a.w, a.w); ffma2(acc01[rr], aa, w01[3]); ffma2(acc23[rr], aa, w23[3]);
            }
        }
    }

    float4 bb = make_float4(0.f, 0.f, 0.f, 0.f);
    if (bias) bb = *(const float4*)(bias + tx * 4);

#pragma unroll
    for (int rr = 0; rr < RPT; rr++) {
        int r = ty * RPT + rr;
        float4 o;
        f2unpack(acc01[rr], o.x, o.y);
        f2unpack(acc23[rr], o.z, o.w);
        o.x += bb.x; o.y += bb.y; o.z += bb.z; o.w += bb.w;
        if (RELU) {
            o.x = fmaxf(o.x, 0.f); o.y = fmaxf(o.y, 0.f);
            o.z = fmaxf(o.z, 0.f); o.w = fmaxf(o.w, 0.f);
        }
        if (out_s) *(float4*)&out_s[r * out_ss + tx * 4] = o;
        if (out_g) *(float4*)(out_g + (size_t)(row0 + r) * out_gs + tx * 4) = o;
    }
}

// ---------------- fused: encoder blocks (0..255) + scan blocks (256..) ------
__global__ void __launch_bounds__(256, 4)
enc_scan_kernel(const float* __restrict__ x,
                const float* __restrict__ b1, const float* __restrict__ b2,
                float* __restrict__ f, float* __restrict__ msg,
                const float* __restrict__ adj)
{
    if ((int)blockIdx.x >= N_NODES / 32) {
        scan_row(adj, (int)blockIdx.x - N_NODES / 32);
        return;
    }

    extern __shared__ float esm[];
    float* s_a = esm;            // 4096: x tile, later h
    float* s_b = esm + 4096;     // 2048: h1
    float* wt  = esm + 6144;     // 8192: double-buffered weight tiles

    const int tid  = threadIdx.x;
    const int row0 = blockIdx.x * 32;

    {   // load x tile [32,32]
        int r = tid >> 3, vv = tid & 7;
        *(float4*)&s_a[r * 32 + vv * 4] =
            *(const float4*)(x + (size_t)(row0 + r) * 32 + vv * 4);
    }
    __syncthreads();

    mlp_gemm<32, 32, 64, true>(s_a, 32, d_wt1, b1, wt, s_b, 64, nullptr, 0, 0);
    __syncthreads();
    mlp_gemm<32, 64, 128, true>(s_b, 64, d_wt2, b2, wt, s_a, 128, f + 128, 256, row0);
    __syncthreads();
    mlp_gemm<32, 128, 128, false>(s_a, 128, d_wtg, nullptr, wt, nullptr, 0, msg, 128, row0);
}

// ---------------- aggregation: one row per 128-thread block (grid=8192) -----
__global__ void __launch_bounds__(128)
agg_kernel(const float* __restrict__ msg, const float* __restrict__ bg,
           float* __restrict__ g)
{
    const int row = blockIdx.x;
    const int c   = threadIdx.x;

    __shared__ int   s_idx[MAXD];
    __shared__ float s_dj [MAXD];

    const int   cnt = d_cnt[row];
    const float di  = d_dinv[row];

    if (c < cnt) {
        int j = d_nbr[(size_t)row * MAXD + c];
        s_idx[c] = j;
        s_dj[c]  = d_dinv[j];
    }
    __syncthreads();

    float a0 = di * msg[(size_t)row * 128 + c];   // self-loop term
    float a1 = 0.f, a2 = 0.f, a3 = 0.f;
    int k = 0;
    for (; k + 3 < cnt; k += 4) {
        a0 += s_dj[k]     * msg[(size_t)s_idx[k]     * 128 + c];
        a1 += s_dj[k + 1] * msg[(size_t)s_idx[k + 1] * 128 + c];
        a2 += s_dj[k + 2] * msg[(size_t)s_idx[k + 2] * 128 + c];
        a3 += s_dj[k + 3] * msg[(size_t)s_idx[k + 3] * 128 + c];
    }
    for (; k < cnt; k++)
        a0 += s_dj[k] * msg[(size_t)s_idx[k] * 128 + c];

    float v = di * ((a0 + a1) + (a2 + a3)) + bg[c];
    g[(size_t)row * 128 + c] = fmaxf(v, 0.f);
}

// ---------------- decoder MLP: 64 rows/block (RPT=8), grid=128 ---------------
// Big row tile amortizes weight LDS over 8 rows/thread -> fma-bound regime.
__global__ void __launch_bounds__(256)
decoder_mlp(const float* __restrict__ g_in,
            const float* __restrict__ bd,  const float* __restrict__ bp1,
            const float* __restrict__ bp2,
            const float* __restrict__ wo,  const float* __restrict__ bo,
            const float* __restrict__ mask,
            const float* __restrict__ f_g,
            float* __restrict__ out)
{
    extern __shared__ float sm[];
    float* s_f  = sm;            // [64][256] 16384 floats
    float* s_t  = sm + 16384;    // [64][128]  8192 floats: g, then p1
    float* wt   = sm + 24576;    // 8192: double-buffered weight tiles
    float* s_wo = sm + 32768;    // [8][64]
    float* s_bo = sm + 33280;    // [8]
    float* s_p2 = s_f;           // reuse after s_f dead: [64][64]

    const int tid  = threadIdx.x;
    const int row0 = blockIdx.x * 64;

    for (int i = tid; i < 64 * 32; i += 256) {   // h half of f
        int r = i >> 5, vv = i & 31;
        *(float4*)&s_f[r * 256 + 128 + vv * 4] =
            *(const float4*)(f_g + (size_t)(row0 + r) * 256 + 128 + vv * 4);
    }
    for (int i = tid; i < 64 * 32; i += 256) {   // g tile
        int r = i >> 5, vv = i & 31;
        *(float4*)&s_t[r * 128 + vv * 4] =
            *(const float4*)(g_in + (size_t)(row0 + r) * 128 + vv * 4);
    }
    for (int i = tid; i < 512; i += 256) s_wo[i] = wo[i];
    if (tid < 8) s_bo[tid] = bo[tid];
    __syncthreads();

    mlp_gemm<64, 128, 128, true>(s_t, 128, d_wtd, bd, wt, s_f, 256, nullptr, 0, 0);
    __syncthreads();
    mlp_gemm<64, 256, 128, true>(s_f, 256, d_wtp1, bp1, wt, s_t, 128, nullptr, 0, 0);
    __syncthreads();
    mlp_gemm<64, 128, 64, true>(s_t, 128, d_wtp2, bp2, wt, s_p2, 64, nullptr, 0, 0);
    __syncthreads();

    {   // out = (p2 @ wo^T + bo) * mask : 64 rows x 8 cols, 2 per thread
        const int m = tid & 7;
#pragma unroll
        for (int half = 0; half < 2; half++) {
            const int r = (tid >> 3) + half * 32;
            float acc = 0.f;
#pragma unroll
            for (int k = 0; k < 64; k++) acc += s_p2[r * 64 + k] * s_wo[m * 64 + k];
            out[(size_t)(row0 + r) * 8 + m] = (acc + s_bo[m]) * mask[row0 + r];
        }
    }
}

// ---------------- launch -----------------------------------------------------
extern "C" void kernel_launch(void* const* d_in, const int* in_sizes, int n_in,
                              void* d_out, int out_size)
{
    const float* x    = (const float*)d_in[0];
    const float* adj  = (const float*)d_in[1];
    const float* mask = (const float*)d_in[2];
    const float* w1   = (const float*)d_in[3];
    const float* b1   = (const float*)d_in[4];
    const float* w2   = (const float*)d_in[5];
    const float* b2   = (const float*)d_in[6];
    const float* wg   = (const float*)d_in[7];
    const float* bg   = (const float*)d_in[8];
    const float* wd   = (const float*)d_in[9];
    const float* bd   = (const float*)d_in[10];
    const float* wp1  = (const float*)d_in[11];
    const float* bp1  = (const float*)d_in[12];
    const float* wp2  = (const float*)d_in[13];
    const float* bp2  = (const float*)d_in[14];
    const float* wo   = (const float*)d_in[15];
    const float* bo   = (const float*)d_in[16];
    float* out = (float*)d_out;

    float *p_msg, *p_f, *p_g;
    cudaGetSymbolAddress((void**)&p_msg, d_msg);
    cudaGetSymbolAddress((void**)&p_f,   d_f);
    cudaGetSymbolAddress((void**)&p_g,   d_g);

    const int ENC_SMEM = (4096 + 2048 + 8192) * 4;              // 57344 B
    const int DEC_SMEM = (16384 + 8192 + 8192 + 512 + 8) * 4;   // 133152 B
    static int smem_set = 0;
    if (!smem_set) {
        cudaFuncSetAttribute(enc_scan_kernel,
                             cudaFuncAttributeMaxDynamicSharedMemorySize, ENC_SMEM);
        cudaFuncSetAttribute(decoder_mlp,
                             cudaFuncAttributeMaxDynamicSharedMemorySize, DEC_SMEM);
        smem_set = 1;
    }

    transpose_weights<<<128, 256>>>(w1, w2, wg, wd, wp1, wp2);
    enc_scan_kernel<<<N_NODES / 32 + N_NODES, 256, ENC_SMEM>>>(
        x, b1, b2, p_f, p_msg, adj);
    agg_kernel<<<N_NODES, 128>>>(p_msg, bg, p_g);
    decoder_mlp<<<N_NODES / 64, 256, DEC_SMEM>>>(
        p_g, bd, bp1, bp2, wo, bo, mask, p_f, out);
}